// round 6
// baseline (speedup 1.0000x reference)
#include <cuda_runtime.h>
#include <math.h>
#include <stdint.h>

#define FULLM 0xffffffffu
#define BMAX 64
#define TMAX 1000
#define UPAD 256
#define EBLANK 0.36787944117144233f
#define E1 2.7182818284590452f

// Scratch (allocation-free rule: __device__ globals).
__device__ float g_loss[BMAX];
__device__ float g_logZ[BMAX * TMAX];
__device__ float g_r[(size_t)BMAX * TMAX * UPAD];   // 64 MB, permuted layout

// ---------------------------------------------------------------------------
// Phase 1: r[b,t,u] = exp(x+1) (masked for u>=tl), logZ[b,t] = log(e^-1+sum exp x)
// One warp per (b,t) row; PERMUTED store: lane's 8 floats at slots lane, 32+lane.
// ---------------------------------------------------------------------------
__global__ void __launch_bounds__(256)
fsloss_prep(const float* __restrict__ attn, const int* __restrict__ text_lens,
            int B, int T, int U)
{
    const int gw   = (blockIdx.x * blockDim.x + threadIdx.x) >> 5;
    const int lane = threadIdx.x & 31;
    if (gw >= B * T) return;
    const int b  = gw / T;
    const int tl = text_lens[b];
    const int u0 = 8 * lane;

    const float2* x2 = (const float2*)(attn + (size_t)gw * U) + 4 * lane;
    float v[8];
    #pragma unroll
    for (int j = 0; j < 4; ++j) {
        float2 d = make_float2(0.f, 0.f);
        if (u0 + 2 * j + 1 < U) d = __ldg(&x2[j]);
        v[2 * j]     = d.x;
        v[2 * j + 1] = d.y;
    }
    float s = 0.f;
    #pragma unroll
    for (int k = 0; k < 8; ++k) {
        float e = (u0 + k < tl) ? __expf(v[k]) : 0.f;
        v[k] = e;
        s += e;
    }
    #pragma unroll
    for (int off = 16; off; off >>= 1) s += __shfl_xor_sync(FULLM, s, off);
    if (lane == 0) g_logZ[gw] = __logf(s + EBLANK);

    float4* dst = (float4*)(g_r + (size_t)gw * UPAD);
    dst[lane]      = make_float4(v[0] * E1, v[1] * E1, v[2] * E1, v[3] * E1);
    dst[32 + lane] = make_float4(v[4] * E1, v[5] * E1, v[6] * E1, v[7] * E1);
}

// ---------------------------------------------------------------------------
// Phase 2: one WARP per batch. 512 states: lane l holds evens e[k]=b[16l+2k],
// odds o[k]=b[16l+2k+1]. Blank factored out: new_e = e + o_prev (no mul);
// new_o = r*(o + e + o_prev). Per-lane pow2 exponent G, renorm every 4 steps.
// ---------------------------------------------------------------------------
__device__ __forceinline__ void fs_step(float e[8], float o[8],
                                        float4 r0, float4 r1, float f)
{
    float prev = __shfl_up_sync(FULLM, o[7], 1) * f;   // lane0: f=0 -> 0
    const float r[8] = {r0.x, r0.y, r0.z, r0.w, r1.x, r1.y, r1.z, r1.w};
    #pragma unroll
    for (int k = 0; k < 8; ++k) {
        float s = e[k] + prev;      // b[s] + b[s-1]
        float t = o[k] + s;         // b[s+1] + b[s] + b[s-1]
        prev = o[k];
        e[k] = s;                   // even update: no multiply
        o[k] = r[k] * t;
    }
}

#define FS_RENORM()                                                           \
    do {                                                                      \
        float me = fmaxf(fmaxf(fmaxf(e[0], e[1]), fmaxf(e[2], e[3])),         \
                         fmaxf(fmaxf(e[4], e[5]), fmaxf(e[6], e[7])));        \
        float mo = fmaxf(fmaxf(fmaxf(o[0], o[1]), fmaxf(o[2], o[3])),         \
                         fmaxf(fmaxf(o[4], o[5]), fmaxf(o[6], o[7])));        \
        float m = fmaxf(me, mo);                                              \
        bool nz = (m > 0.f);                                                  \
        if (nz) {                                                             \
            int Ee = (int)((__float_as_uint(m) >> 23) & 255u);                \
            float sc = __uint_as_float((unsigned)(254 - Ee) << 23);           \
            _Pragma("unroll")                                                 \
            for (int j = 0; j < 8; ++j) { e[j] *= sc; o[j] *= sc; }           \
            G += Ee - 127;                                                    \
        }                                                                     \
        int val = (G << 1) | (nz ? 1 : 0);                                    \
        int up  = __shfl_up_sync(FULLM, val, 1);                              \
        int Gup = up >> 1;                                                    \
        if (!nz && lane > 0) G = Gup;                                         \
        int D = Gup - G;                                                      \
        if (D > 127) D = 127;                                                 \
        f = (lane == 0 || D < -126) ? 0.f                                     \
            : __uint_as_float((unsigned)(D + 127) << 23);                     \
    } while (0)

#define FS_CAPTURE()                                                          \
    do {                                                                      \
        _Pragma("unroll")                                                     \
        for (int k = 0; k < 8; ++k)                                           \
            if (16 * lane + 2 * k == S) fincap = e[k] + o[k];                 \
        Gcap = G;                                                             \
    } while (0)

__global__ void __launch_bounds__(32)
fsloss_scan(const int* __restrict__ text_lens, const int* __restrict__ mel_lens,
            int T)
{
    const int b = blockIdx.x, lane = threadIdx.x;
    const int tl = text_lens[b], ml = mel_lens[b];
    const int S = 2 * tl, mlm1 = ml - 1;
    const float4* P  = (const float4*)(g_r + (size_t)b * T * UPAD);
    const float4* p0 = P + lane;        // permuted: slot lane
    const float4* p1 = P + 32 + lane;   // permuted: slot 32+lane

    float e[8], o[8];
    #pragma unroll
    for (int j = 0; j < 8; ++j) { e[j] = 0.f; o[j] = 0.f; }
    if (lane == 0) e[0] = 1.f;          // state 0

    int   G = 0, Gcap = 0;
    float fincap = 0.f;
    float f = (lane == 0) ? 0.f : 1.f;

    float4 A0[4], A1[4], B0[4], B1[4];
    #pragma unroll
    for (int r = 0; r < 4; ++r) { A0[r] = p0[r * 64];       A1[r] = p1[r * 64]; }
    #pragma unroll
    for (int r = 0; r < 4; ++r) { B0[r] = p0[(r + 4) * 64]; B1[r] = p1[(r + 4) * 64]; }

    const int full = mlm1 >> 3;
    const float4* q0 = p0 + 512;        // row 8
    const float4* q1 = p1 + 512;

    for (int blk = 0; blk < full; ++blk) {
        fs_step(e, o, A0[0], A1[0], f);
        fs_step(e, o, A0[1], A1[1], f);
        fs_step(e, o, A0[2], A1[2], f);
        fs_step(e, o, A0[3], A1[3], f);
        #pragma unroll
        for (int r = 0; r < 4; ++r) { A0[r] = q0[r * 64]; A1[r] = q1[r * 64]; }
        FS_RENORM();
        fs_step(e, o, B0[0], B1[0], f);
        fs_step(e, o, B0[1], B1[1], f);
        fs_step(e, o, B0[2], B1[2], f);
        fs_step(e, o, B0[3], B1[3], f);
        #pragma unroll
        for (int r = 0; r < 4; ++r) { B0[r] = q0[(r + 4) * 64]; B1[r] = q1[(r + 4) * 64]; }
        FS_RENORM();
        q0 += 512; q1 += 512;
    }

    // tail: steps 8*full .. mlm1 (rows already resident in A/B)
    {
        const int rem = mlm1 - 8 * full;  // 0..7
        #pragma unroll
        for (int r = 0; r < 8; ++r) {
            float4 t0 = (r < 4) ? A0[r & 3] : B0[r & 3];
            float4 t1 = (r < 4) ? A1[r & 3] : B1[r & 3];
            fs_step(e, o, t0, t1, f);
            if (r == rem) { FS_CAPTURE(); break; }
            if (r == 3) FS_RENORM();
        }
    }

    // epilogue: Zsum = sum_{t<ml} logZ_t   (log c = -ml - Zsum)
    const float* lz = g_logZ + (size_t)b * T;
    double zs = 0.0;
    for (int i = lane; i < ml; i += 32) zs += (double)__ldg(&lz[i]);
    #pragma unroll
    for (int off = 16; off; off >>= 1)
        zs += __shfl_xor_sync(FULLM, zs, off);

    // exactly one lane holds fincap (states S and S-1 share a lane)
    double lv = (fincap > 0.f)
        ? (log((double)fincap) + (double)Gcap * 0.6931471805599453)
        : -1e300;
    #pragma unroll
    for (int off = 16; off; off >>= 1)
        lv = fmax(lv, __shfl_xor_sync(FULLM, lv, off));

    if (lane == 0) {
        float loss = 0.f;
        if (lv > -1e299) {
            double fin = lv - (double)ml - zs;   // + log c
            loss = (float)(-fin / (double)tl);
        }
        g_loss[b] = loss;
    }
}

__global__ void fsloss_reduce(float* __restrict__ out, int B)
{
    __shared__ float ws[2];
    float v = (threadIdx.x < B) ? g_loss[threadIdx.x] : 0.0f;
    #pragma unroll
    for (int off = 16; off; off >>= 1)
        v += __shfl_xor_sync(FULLM, v, off);
    if ((threadIdx.x & 31) == 0) ws[threadIdx.x >> 5] = v;
    __syncthreads();
    if (threadIdx.x == 0) out[0] = (ws[0] + ws[1]) / (float)B;
}

extern "C" void kernel_launch(void* const* d_in, const int* in_sizes, int n_in,
                              void* d_out, int out_size)
{
    const float* attn = (const float*)d_in[0];
    const int*   tl   = (const int*)d_in[1];
    const int*   ml   = (const int*)d_in[2];
    int B = in_sizes[1];
    const int U = 250;
    int T = in_sizes[0] / (B * U);

    int rows = B * T;
    fsloss_prep<<<(rows * 32 + 255) / 256, 256>>>(attn, tl, B, T, U);
    fsloss_scan<<<B, 32>>>(tl, ml, T);
    fsloss_reduce<<<1, 64>>>((float*)d_out, B);
}

// round 7
// speedup vs baseline: 1.3464x; 1.3464x over previous
#include <cuda_runtime.h>
#include <math.h>
#include <stdint.h>

#define FULLM 0xffffffffu
#define BMAX 64
#define TMAX 1000
#define UPAD 256

// Scratch (allocation-free rule: __device__ globals).
__device__ float g_loss[BMAX];
__device__ float g_logZ[BMAX * TMAX];
__device__ float g_r[(size_t)BMAX * TMAX * UPAD];   // 64 MB, permuted layout

// ---------------------------------------------------------------------------
// Phase 1: r[b,t,u] = exp(x+1) (masked for u>=tl); logZ = log1p(sum r) - 1.
// One warp per (b,t) row; PERMUTED store: lane's 8 floats at slots lane, 32+lane.
// ---------------------------------------------------------------------------
__global__ void __launch_bounds__(256)
fsloss_prep(const float* __restrict__ attn, const int* __restrict__ text_lens,
            int B, int T, int U)
{
    const int gw   = (blockIdx.x * blockDim.x + threadIdx.x) >> 5;
    const int lane = threadIdx.x & 31;
    if (gw >= B * T) return;
    const int b  = gw / T;
    const int tl = text_lens[b];
    const int u0 = 8 * lane;

    const float2* x2 = (const float2*)(attn + (size_t)gw * U) + 4 * lane;
    float v[8];
    #pragma unroll
    for (int j = 0; j < 4; ++j) {
        float2 d = make_float2(0.f, 0.f);
        if (u0 + 2 * j + 1 < U) d = __ldg(&x2[j]);
        v[2 * j]     = d.x;
        v[2 * j + 1] = d.y;
    }
    float s = 0.f;
    #pragma unroll
    for (int k = 0; k < 8; ++k) {
        float e = (u0 + k < tl) ? __expf(v[k] + 1.f) : 0.f;  // r = exp(x+1)
        v[k] = e;
        s += e;
    }
    #pragma unroll
    for (int off = 16; off; off >>= 1) s += __shfl_xor_sync(FULLM, s, off);
    if (lane == 0) g_logZ[gw] = __logf(s + 1.f) - 1.f;  // log(e^-1 + sum exp x)

    float4* dst = (float4*)(g_r + (size_t)gw * UPAD);
    dst[lane]      = make_float4(v[0], v[1], v[2], v[3]);
    dst[32 + lane] = make_float4(v[4], v[5], v[6], v[7]);
}

// ---------------------------------------------------------------------------
// Phase 2: one WARP per batch. 512 states: lane l holds e[k]=b[16l+2k],
// o[k]=b[16l+2k+1]. Blank factored out: new_e = e + o_prev; new_o = r*(o+e+o_prev).
// Per-lane pow2 exponent G, renorm every 8 steps. 16-row prefetch pipeline.
// ---------------------------------------------------------------------------
__device__ __forceinline__ void fs_step(float e[8], float o[8],
                                        float4 r0, float4 r1, float f)
{
    float prev = __shfl_up_sync(FULLM, o[7], 1) * f;   // lane0: f=0 -> 0
    const float r[8] = {r0.x, r0.y, r0.z, r0.w, r1.x, r1.y, r1.z, r1.w};
    #pragma unroll
    for (int k = 0; k < 8; ++k) {
        float s = e[k] + prev;      // b[s] + b[s-1]
        float t = o[k] + s;         // b[s+1] + b[s] + b[s-1]
        prev = o[k];
        e[k] = s;                   // even update: no multiply
        o[k] = r[k] * t;
    }
}

#define FS_RENORM()                                                           \
    do {                                                                      \
        float me = fmaxf(fmaxf(fmaxf(e[0], e[1]), fmaxf(e[2], e[3])),         \
                         fmaxf(fmaxf(e[4], e[5]), fmaxf(e[6], e[7])));        \
        float mo = fmaxf(fmaxf(fmaxf(o[0], o[1]), fmaxf(o[2], o[3])),         \
                         fmaxf(fmaxf(o[4], o[5]), fmaxf(o[6], o[7])));        \
        float m = fmaxf(me, mo);                                              \
        bool nz = (m > 0.f);                                                  \
        if (nz) {                                                             \
            int Ee = (int)((__float_as_uint(m) >> 23) & 255u);                \
            float sc = __uint_as_float((unsigned)(254 - Ee) << 23);           \
            _Pragma("unroll")                                                 \
            for (int j = 0; j < 8; ++j) { e[j] *= sc; o[j] *= sc; }           \
            G += Ee - 127;                                                    \
        }                                                                     \
        int val = (G << 1) | (nz ? 1 : 0);                                    \
        int up  = __shfl_up_sync(FULLM, val, 1);                              \
        int Gup = up >> 1;                                                    \
        if (!nz && lane > 0) G = Gup;                                         \
        int D = Gup - G;                                                      \
        if (D > 127) D = 127;                                                 \
        f = (lane == 0 || D < -126) ? 0.f                                     \
            : __uint_as_float((unsigned)(D + 127) << 23);                     \
    } while (0)

// capture states S (even, e[k] at 16l+2k==S) and S-1 (odd, o[k] at 16l+2k==S-2).
// They may live in different lanes (S % 16 == 0) -> lse over lanes in epilogue.
#define FS_CAPTURE()                                                          \
    do {                                                                      \
        _Pragma("unroll")                                                     \
        for (int k = 0; k < 8; ++k) {                                         \
            int se_ = 16 * lane + 2 * k;                                      \
            if (se_ == S)     fincap += e[k];                                 \
            if (se_ == S - 2) fincap += o[k];                                 \
        }                                                                     \
        Gcap = G;                                                             \
    } while (0)

__global__ void __launch_bounds__(32)
fsloss_scan(const int* __restrict__ text_lens, const int* __restrict__ mel_lens,
            int T)
{
    const int b = blockIdx.x, lane = threadIdx.x;
    const int tl = text_lens[b], ml = mel_lens[b];
    const int S = 2 * tl, mlm1 = ml - 1;
    const float4* P  = (const float4*)(g_r + (size_t)b * T * UPAD);
    const float4* p0 = P + lane;        // permuted: slot lane
    const float4* p1 = P + 32 + lane;   // permuted: slot 32+lane

    float e[8], o[8];
    #pragma unroll
    for (int j = 0; j < 8; ++j) { e[j] = 0.f; o[j] = 0.f; }
    if (lane == 0) e[0] = 1.f;          // state 0

    int   G = 0, Gcap = 0;
    float fincap = 0.f;
    float f = (lane == 0) ? 0.f : 1.f;

    // two 8-row buffer sets; 16 rows in flight
    float4 Ax[8], Ay[8], Bx[8], By[8];
    #pragma unroll
    for (int r = 0; r < 8; ++r) { Ax[r] = __ldg(p0 + r * 64);
                                  Ay[r] = __ldg(p1 + r * 64); }
    #pragma unroll
    for (int r = 0; r < 8; ++r) { Bx[r] = __ldg(p0 + (r + 8) * 64);
                                  By[r] = __ldg(p1 + (r + 8) * 64); }

    const int full = mlm1 >> 4;          // complete 16-step superblocks

    for (int i = 0; i < full; ++i) {
        #pragma unroll
        for (int r = 0; r < 8; ++r) fs_step(e, o, Ax[r], Ay[r], f);
        {   // reload A <- rows 16(i+1)..+7 (clamped rows are never consumed)
            int rb = 16 * (i + 1); if (rb > T - 8) rb = T - 8;
            const float4* qa0 = P + (size_t)rb * 64 + lane;
            const float4* qa1 = qa0 + 32;
            #pragma unroll
            for (int r = 0; r < 8; ++r) { Ax[r] = __ldg(qa0 + r * 64);
                                          Ay[r] = __ldg(qa1 + r * 64); }
        }
        FS_RENORM();
        #pragma unroll
        for (int r = 0; r < 8; ++r) fs_step(e, o, Bx[r], By[r], f);
        {   // reload B <- rows 16(i+1)+8..+15
            int rb = 16 * (i + 1) + 8; if (rb > T - 8) rb = T - 8;
            const float4* qb0 = P + (size_t)rb * 64 + lane;
            const float4* qb1 = qb0 + 32;
            #pragma unroll
            for (int r = 0; r < 8; ++r) { Bx[r] = __ldg(qb0 + r * 64);
                                          By[r] = __ldg(qb1 + r * 64); }
        }
        FS_RENORM();
    }

    // tail: steps 16*full .. mlm1 (1..16 steps); rows resident in A/B.
    {
        const int rem = mlm1 - 16 * full;   // 0..15
        #pragma unroll
        for (int r = 0; r < 16; ++r) {
            float4 t0 = (r < 8) ? Ax[r & 7] : Bx[r & 7];
            float4 t1 = (r < 8) ? Ay[r & 7] : By[r & 7];
            fs_step(e, o, t0, t1, f);
            if (r == rem) { FS_CAPTURE(); break; }
            if (r == 7) FS_RENORM();
        }
    }

    // epilogue: Zsum = sum_{t<ml} logZ_t  (log c = -ml - Zsum)
    const float* lz = g_logZ + (size_t)b * T;
    double zs = 0.0, zs2 = 0.0;
    int i2 = lane;
    for (; i2 + 32 < ml; i2 += 64) {
        zs  += (double)__ldg(&lz[i2]);
        zs2 += (double)__ldg(&lz[i2 + 32]);
    }
    if (i2 < ml) zs += (double)__ldg(&lz[i2]);
    zs += zs2;
    #pragma unroll
    for (int off = 16; off; off >>= 1)
        zs += __shfl_xor_sync(FULLM, zs, off);

    // lse over lanes (up to 2 lanes hold fin terms with different exponents)
    double lv = (fincap > 0.f)
        ? (log((double)fincap) + (double)Gcap * 0.6931471805599453)
        : -1e300;
    double mx = lv;
    #pragma unroll
    for (int off = 16; off; off >>= 1)
        mx = fmax(mx, __shfl_xor_sync(FULLM, mx, off));
    double ex = (lv > -1e299) ? exp(lv - mx) : 0.0;
    #pragma unroll
    for (int off = 16; off; off >>= 1)
        ex += __shfl_xor_sync(FULLM, ex, off);

    if (lane == 0) {
        float loss = 0.f;
        if (mx > -1e299) {
            double fin = (mx + log(ex)) - (double)ml - zs;
            loss = (float)(-fin / (double)tl);
        }
        g_loss[b] = loss;
    }
}

__global__ void fsloss_reduce(float* __restrict__ out, int B)
{
    __shared__ float ws[2];
    float v = (threadIdx.x < B) ? g_loss[threadIdx.x] : 0.0f;
    #pragma unroll
    for (int off = 16; off; off >>= 1)
        v += __shfl_xor_sync(FULLM, v, off);
    if ((threadIdx.x & 31) == 0) ws[threadIdx.x >> 5] = v;
    __syncthreads();
    if (threadIdx.x == 0) out[0] = (ws[0] + ws[1]) / (float)B;
}

extern "C" void kernel_launch(void* const* d_in, const int* in_sizes, int n_in,
                              void* d_out, int out_size)
{
    const float* attn = (const float*)d_in[0];
    const int*   tl   = (const int*)d_in[1];
    const int*   ml   = (const int*)d_in[2];
    int B = in_sizes[1];
    const int U = 250;
    int T = in_sizes[0] / (B * U);

    int rows = B * T;
    fsloss_prep<<<(rows * 32 + 255) / 256, 256>>>(attn, tl, B, T, U);
    fsloss_scan<<<B, 32>>>(tl, ml, T);
    fsloss_reduce<<<1, 64>>>((float*)d_out, B);
}